// round 5
// baseline (speedup 1.0000x reference)
#include <cuda_runtime.h>
#include <math.h>

#define Bb 4
#define Ss 2048
#define Dd 1024
#define Hh 16
#define HDd 64
#define Mm 4

// ---------------- scratch (device globals; no allocs allowed) ----------------
__device__ float g_stacked[(size_t)Bb * Mm * Ss * Dd];
__device__ float g_Q[(size_t)Bb * Mm * Ss * Dd];
__device__ float g_K[(size_t)Bb * Mm * Ss * Dd];
__device__ float g_V[(size_t)Bb * Mm * Ss * Dd];
__device__ float g_fused[(size_t)Bb * Ss * Dd];

// Cantor routes, computed with exact double semantics:
// (1/3)*3 == 1.0 and (2/3)*3 == 2.0 exactly in IEEE double, so
// coords = [0, 0, 0.5, 0.99609375]
// dist rows -> stable argsort -> first 3:
//   row0: [0,1,2]  row1: [0,1,2]  row2: [2,3,0]  row3: [3,2,0]
__constant__ int c_routes[4][3] = {{0, 1, 2}, {0, 1, 2}, {2, 3, 0}, {3, 2, 0}};

// ---------------- zero fill of stacked (pad regions must be exactly 0) -------
__global__ void zero_stacked_kernel() {
    size_t n4 = ((size_t)Bb * Mm * Ss * Dd) / 4;
    size_t i = (size_t)blockIdx.x * blockDim.x + threadIdx.x;
    float4 z = make_float4(0.f, 0.f, 0.f, 0.f);
    float4* p = reinterpret_cast<float4*>(g_stacked);
    for (; i < n4; i += (size_t)gridDim.x * blockDim.x) p[i] = z;
}

// ---------------- generic C = A @ W^T + bias (+bias2), N fixed = 1024 --------
// Output row r is stored at C + (r/sl)*outerStride + modOffset + (r%sl)*1024.
// For identity mapping pass sl >= Mrows, outerStride = 0, modOffset = 0.
__global__ void __launch_bounds__(256) sgemm_tn(
    const float* __restrict__ A, int lda,
    const float* __restrict__ W,      // N x K row-major (N = 1024)
    const float* __restrict__ bias,   // N
    const float* __restrict__ bias2,  // N or nullptr
    float* __restrict__ C,
    int Mrows, int K,
    int sl, long long outerStride, long long modOffset)
{
    const int N = 1024;
    __shared__ float As[8][128];
    __shared__ float Bs[8][128];

    int tid = threadIdx.x;
    int bm = blockIdx.y * 128;
    int bn = blockIdx.x * 128;

    int lrow = tid >> 1;          // 0..127
    int lcol = (tid & 1) * 4;     // 0 or 4
    int tx = tid & 15;            // 0..15
    int ty = tid >> 4;            // 0..15

    float acc[8][8];
#pragma unroll
    for (int i = 0; i < 8; i++)
#pragma unroll
        for (int j = 0; j < 8; j++) acc[i][j] = 0.f;

    bool aValid = (bm + lrow) < Mrows;
    const float* Aptr = A + (long long)(bm + lrow) * lda + lcol;
    const float* Wptr = W + (long long)(bn + lrow) * K + lcol;

    for (int k0 = 0; k0 < K; k0 += 8) {
        float4 av = aValid ? *(const float4*)(Aptr + k0) : make_float4(0.f, 0.f, 0.f, 0.f);
        float4 bv = *(const float4*)(Wptr + k0);
        As[lcol + 0][lrow] = av.x;
        As[lcol + 1][lrow] = av.y;
        As[lcol + 2][lrow] = av.z;
        As[lcol + 3][lrow] = av.w;
        Bs[lcol + 0][lrow] = bv.x;
        Bs[lcol + 1][lrow] = bv.y;
        Bs[lcol + 2][lrow] = bv.z;
        Bs[lcol + 3][lrow] = bv.w;
        __syncthreads();

#pragma unroll
        for (int kk = 0; kk < 8; kk++) {
            float ar[8], br[8];
            *(float4*)&ar[0] = *(const float4*)&As[kk][ty * 8];
            *(float4*)&ar[4] = *(const float4*)&As[kk][ty * 8 + 4];
            *(float4*)&br[0] = *(const float4*)&Bs[kk][tx * 8];
            *(float4*)&br[4] = *(const float4*)&Bs[kk][tx * 8 + 4];
#pragma unroll
            for (int i = 0; i < 8; i++)
#pragma unroll
                for (int j = 0; j < 8; j++) acc[i][j] += ar[i] * br[j];
        }
        __syncthreads();
    }

#pragma unroll
    for (int i = 0; i < 8; i++) {
        int r = bm + ty * 8 + i;
        if (r < Mrows) {
            long long orow = (long long)(r / sl) * outerStride + modOffset +
                             (long long)(r % sl) * N;
#pragma unroll
            for (int j = 0; j < 8; j += 4) {
                int c = bn + tx * 8 + j;
                float4 bv = *(const float4*)&bias[c];
                float4 b2 = bias2 ? *(const float4*)&bias2[c]
                                  : make_float4(0.f, 0.f, 0.f, 0.f);
                float4 o;
                o.x = acc[i][j + 0] + bv.x + b2.x;
                o.y = acc[i][j + 1] + bv.y + b2.y;
                o.z = acc[i][j + 2] + bv.z + b2.z;
                o.w = acc[i][j + 3] + bv.w + b2.w;
                *(float4*)&C[orow + c] = o;
            }
        }
    }
}

// ---------------- fused 3-way cross-modality attention + mean over m ---------
// grid = (S, H/4, B), block = 128 (one warp per head). Lane l covers d = l, l+32.
__global__ void __launch_bounds__(128) attn_fuse_kernel(const float* __restrict__ tptr)
{
    int s = blockIdx.x;
    int b = blockIdx.z;
    int h = blockIdx.y * 4 + (threadIdx.x >> 5);
    int lane = threadIdx.x & 31;

    float invscale = 1.f / (8.f * fabsf(*tptr));

    int col = h * HDd + lane;
    long long base = ((long long)b * Mm) * Ss * Dd + (long long)s * Dd + col;

    float q0[4], q1[4], k0[4], k1[4], v0[4], v1[4];
#pragma unroll
    for (int m = 0; m < 4; m++) {
        long long idx = base + (long long)m * Ss * Dd;
        q0[m] = g_Q[idx];      q1[m] = g_Q[idx + 32];
        k0[m] = g_K[idx];      k1[m] = g_K[idx + 32];
        v0[m] = g_V[idx];      v1[m] = g_V[idx + 32];
    }

    float acc0 = 0.f, acc1 = 0.f;
#pragma unroll
    for (int m = 0; m < 4; m++) {
        float sc[3];
#pragma unroll
        for (int w = 0; w < 3; w++) {
            int r = c_routes[m][w];
            float p = q0[m] * k0[r] + q1[m] * k1[r];
#pragma unroll
            for (int o = 16; o > 0; o >>= 1) p += __shfl_xor_sync(0xffffffffu, p, o);
            sc[w] = p * invscale;
        }
        float mx = fmaxf(sc[0], fmaxf(sc[1], sc[2]));
        float e0 = expf(sc[0] - mx), e1 = expf(sc[1] - mx), e2 = expf(sc[2] - mx);
        float inv = 1.f / (e0 + e1 + e2);
        e0 *= inv; e1 *= inv; e2 *= inv;
        int r0 = c_routes[m][0], r1 = c_routes[m][1], r2 = c_routes[m][2];
        acc0 += e0 * v0[r0] + e1 * v0[r1] + e2 * v0[r2];
        acc1 += e0 * v1[r0] + e1 * v1[r1] + e2 * v1[r2];
    }

    long long fidx = ((long long)b * Ss + s) * Dd + col;
    g_fused[fidx]      = acc0 * 0.25f;
    g_fused[fidx + 32] = acc1 * 0.25f;
}

// ---------------- host launcher ---------------------------------------------
extern "C" void kernel_launch(void* const* d_in, const int* in_sizes, int n_in,
                              void* d_out, int out_size)
{
    // Resolve input ordering: setup-dict order has W_text (1024*768) at index 1,
    // reference-signature order has image (4*1024*1024) at index 1.
    bool dictOrder = (in_sizes[1] == 1024 * 768);

    int xi[4], wi[4], bi[4];
    if (dictOrder) {
        int x[4] = {0, 3, 6, 9}, w[4] = {1, 4, 7, 10}, bidx[4] = {2, 5, 8, 11};
        for (int i = 0; i < 4; i++) { xi[i] = x[i]; wi[i] = w[i]; bi[i] = bidx[i]; }
    } else {
        int x[4] = {0, 1, 2, 3}, w[4] = {4, 6, 8, 10}, bidx[4] = {5, 7, 9, 11};
        for (int i = 0; i < 4; i++) { xi[i] = x[i]; wi[i] = w[i]; bi[i] = bidx[i]; }
    }
    const float* X[4];  const float* Wm[4]; const float* bm_[4];
    for (int i = 0; i < 4; i++) {
        X[i]   = (const float*)d_in[xi[i]];
        Wm[i]  = (const float*)d_in[wi[i]];
        bm_[i] = (const float*)d_in[bi[i]];
    }
    const float* mod_emb = (const float*)d_in[12];
    const float* Wq = (const float*)d_in[13]; const float* bq = (const float*)d_in[14];
    const float* Wk = (const float*)d_in[15]; const float* bk = (const float*)d_in[16];
    const float* Wv = (const float*)d_in[17]; const float* bv = (const float*)d_in[18];
    const float* Wo = (const float*)d_in[19]; const float* bo = (const float*)d_in[20];
    const float* tptr = (const float*)d_in[21];

    float *stacked, *Qb, *Kb, *Vb, *fusedb;
    cudaGetSymbolAddress((void**)&stacked, g_stacked);
    cudaGetSymbolAddress((void**)&Qb, g_Q);
    cudaGetSymbolAddress((void**)&Kb, g_K);
    cudaGetSymbolAddress((void**)&Vb, g_V);
    cudaGetSymbolAddress((void**)&fusedb, g_fused);

    // 1) zero-fill stacked (pad regions must be zero)
    zero_stacked_kernel<<<8192, 256>>>();

    // 2) modality projections: stacked[b, i, s, :] = x_i @ W_i^T + b_i + mod_emb[i]
    const int dims[4] = {768, 1024, 512, 2048};
    const int sls[4]  = {2048, 1024, 1500, 512};
    for (int i = 0; i < 4; i++) {
        int Mr = Bb * sls[i];
        dim3 grid(1024 / 128, (Mr + 127) / 128);
        sgemm_tn<<<grid, 256>>>(X[i], dims[i], Wm[i], bm_[i],
                                mod_emb + (long long)i * Dd,
                                stacked, Mr, dims[i],
                                sls[i], (long long)Mm * Ss * Dd,
                                (long long)i * Ss * Dd);
    }

    // 3) QKV projections on flattened stacked (B*M*S, D)
    {
        int Mr = Bb * Mm * Ss;
        dim3 grid(1024 / 128, Mr / 128);
        sgemm_tn<<<grid, 256>>>(stacked, Dd, Wq, bq, nullptr, Qb, Mr, Dd, Mr, 0, 0);
        sgemm_tn<<<grid, 256>>>(stacked, Dd, Wk, bk, nullptr, Kb, Mr, Dd, Mr, 0, 0);
        sgemm_tn<<<grid, 256>>>(stacked, Dd, Wv, bv, nullptr, Vb, Mr, Dd, Mr, 0, 0);
    }

    // 4) fused routed attention + mean over modalities -> g_fused (B, S, D)
    {
        dim3 grid(Ss, Hh / 4, Bb);
        attn_fuse_kernel<<<grid, 128>>>(tptr);
    }

    // 5) output projection: out = fused @ Wo^T + bo
    {
        int Mr = Bb * Ss;
        dim3 grid(1024 / 128, Mr / 128);
        sgemm_tn<<<grid, 256>>>(fusedb, Dd, Wo, bo, nullptr,
                                (float*)d_out, Mr, Dd, Mr, 0, 0);
    }
}

// round 10
// speedup vs baseline: 2.6189x; 2.6189x over previous
#include <cuda_runtime.h>
#include <cuda_bf16.h>
#include <math.h>
#include <stdint.h>

#define Bb 4
#define Ss 2048
#define Dd 1024
#define Hh 16
#define Mm 4

#define BMSD (4LL*4*2048*1024)
#define BSD  (4LL*2048*1024)

static const int h_dims[4] = {768, 1024, 512, 2048};
static const int h_sls[4]  = {2048, 1024, 1500, 512};
static const long long h_xoff[4] = {0, 6291456, 10485760, 13557760};
#define XTOT 17752064
static const long long h_woff[8] = {0, 786432, 1835008, 2359296, 4456448, 5505024, 6553600, 7602176};
#define WTOT 8650752

// ---------------- scratch (device globals) -----------------------------------
__device__ __nv_bfloat16 g_xhi[XTOT], g_xlo[XTOT];
__device__ __nv_bfloat16 g_whi[WTOT], g_wlo[WTOT];
__device__ __nv_bfloat16 g_shi[BMSD], g_slo[BMSD];
__device__ float g_Q[BMSD], g_K[BMSD], g_V[BMSD];
__device__ __nv_bfloat16 g_fhi[BSD], g_flo[BSD];

// Cantor routes (exact-double semantics): coords = [0, 0, 0.5, 0.99609375]
__constant__ int c_routes[4][3] = {{0, 1, 2}, {0, 1, 2}, {2, 3, 0}, {3, 2, 0}};
__constant__ int c_sl[4] = {2048, 1024, 1500, 512};

// ---------------- helpers -----------------------------------------------------
__device__ __forceinline__ uint32_t smem_u32(const void* p) {
    uint32_t a;
    asm("{ .reg .u64 t; cvta.to.shared.u64 t, %1; cvt.u32.u64 %0, t; }" : "=r"(a) : "l"(p));
    return a;
}

#define CPA(sa, ga, sz) \
    asm volatile("cp.async.cg.shared.global [%0], [%1], 16, %2;" \
                 :: "r"(sa), "l"(ga), "r"(sz) : "memory")
#define CPA_COMMIT() asm volatile("cp.async.commit_group;" ::: "memory")
#define CPA_WAIT1()  asm volatile("cp.async.wait_group 1;" ::: "memory")
#define CPA_WAIT0()  asm volatile("cp.async.wait_group 0;" ::: "memory")

#define LDSM4(r0, r1, r2, r3, addr) \
    asm volatile("ldmatrix.sync.aligned.m8n8.x4.shared.b16 {%0,%1,%2,%3}, [%4];" \
                 : "=r"(r0), "=r"(r1), "=r"(r2), "=r"(r3) : "r"(addr))

#define MMA16816(d, a, b) \
    asm volatile("mma.sync.aligned.m16n8k16.row.col.f32.bf16.bf16.f32 " \
                 "{%0,%1,%2,%3}, {%4,%5,%6,%7}, {%8,%9}, {%0,%1,%2,%3};" \
                 : "+f"((d)[0]), "+f"((d)[1]), "+f"((d)[2]), "+f"((d)[3]) \
                 : "r"((a)[0]), "r"((a)[1]), "r"((a)[2]), "r"((a)[3]), \
                   "r"((b)[0]), "r"((b)[1]))

// ---------------- bf16 hi/lo split -------------------------------------------
__global__ void split_kernel(const float* __restrict__ in, __nv_bfloat16* __restrict__ hi,
                             __nv_bfloat16* __restrict__ lo, int n) {
    for (int i = blockIdx.x * blockDim.x + threadIdx.x; i < n; i += gridDim.x * blockDim.x) {
        float x = in[i];
        __nv_bfloat16 h = __float2bfloat16(x);
        hi[i] = h;
        lo[i] = __float2bfloat16(x - __bfloat162float(h));
    }
}

// ---------------- bf16x2 mma.sync GEMM: C = A @ W^T (+bias,+bias2) -----------
// 128x128 tile, 256 threads (8 warps, warp tile 64x32), BK=32, cp.async x2 stages.
// SMEM pitch 40 bf16 (80B) for conflict-free ldmatrix.
// A row r: (r/a_sl)*a_instride + a_inoff + (r%a_sl)*lda   (element offsets)
// C row r: (r/c_sl)*c_outer + c_modoff + (r%c_sl)*1024
#define PITCHB 80
#define ASZ (128 * PITCHB)          // 10240 per array
#define STAGE_SZ (4 * ASZ)          // Ah, Al, Bh, Bl
#define GEMM_SMEM (2 * STAGE_SZ)    // 81920

__global__ void __launch_bounds__(256, 1) gemm_bf16x2(
    const __nv_bfloat16* __restrict__ Ahi, const __nv_bfloat16* __restrict__ Alo,
    long long a_instride, long long a_inoff, int a_sl, int lda,
    const __nv_bfloat16* __restrict__ Bhi, const __nv_bfloat16* __restrict__ Blo,
    const float* __restrict__ bias, const float* __restrict__ bias2,
    float* __restrict__ Cp, __nv_bfloat16* __restrict__ Chi, __nv_bfloat16* __restrict__ Clo,
    int Mrows, int K, int c_slv, long long c_outer, long long c_modoff)
{
    extern __shared__ char smem[];
    const uint32_t sbase = smem_u32(smem);
    int tid = threadIdx.x, wid = tid >> 5, lane = tid & 31;
    int warp_m = wid & 1, warp_n = wid >> 1;
    int bm = blockIdx.y * 128, bn = blockIdx.x * 128;

    // ---- load slots: 2 per thread per array (128 rows x 4 chunks of 16B) ----
    uint32_t smoff[2];
    long long abyte[2], bbyte[2];
    uint32_t asz[2];
#pragma unroll
    for (int i = 0; i < 2; i++) {
        int s = tid + i * 256;
        int row = s >> 2, ch = s & 3;
        smoff[i] = (uint32_t)(row * PITCHB + ch * 16);
        int gr = bm + row;
        bool av = gr < Mrows;
        asz[i] = av ? 16u : 0u;
        abyte[i] = av ? ((long long)(gr / a_sl) * a_instride + a_inoff +
                         (long long)(gr % a_sl) * lda + ch * 8) * 2
                      : 0;
        bbyte[i] = ((long long)(bn + row) * K + ch * 8) * 2;
    }

    const int NK = K >> 5;

    // prologue: stages 0,1
#pragma unroll
    for (int p = 0; p < 2; p++) {
        uint32_t st = sbase + p * STAGE_SZ;
        long long kb = (long long)(p * 32) * 2;
#pragma unroll
        for (int i = 0; i < 2; i++) {
            CPA(st + 0 * ASZ + smoff[i], (const char*)Ahi + abyte[i] + kb, asz[i]);
            CPA(st + 1 * ASZ + smoff[i], (const char*)Alo + abyte[i] + kb, asz[i]);
            CPA(st + 2 * ASZ + smoff[i], (const char*)Bhi + bbyte[i] + kb, 16u);
            CPA(st + 3 * ASZ + smoff[i], (const char*)Blo + bbyte[i] + kb, 16u);
        }
        CPA_COMMIT();
    }

    float acc[4][4][4];
#pragma unroll
    for (int a = 0; a < 4; a++)
#pragma unroll
        for (int b = 0; b < 4; b++)
#pragma unroll
            for (int c = 0; c < 4; c++) acc[a][b][c] = 0.f;

    // ldmatrix lane addressing
    int lrow = lane & 7, lsel = lane >> 3;
    int arow0 = warp_m * 64 + ((lsel & 1) << 3) + lrow;
    int brow0 = warp_n * 32 + ((lsel & 1) << 3) + lrow;
    int colp  = (lsel >> 1) << 3;    // 0 or 8 (element col within k16)

    for (int kt = 0; kt < NK; ++kt) {
        CPA_WAIT1();
        __syncthreads();
        uint32_t st = sbase + (kt & 1) * STAGE_SZ;
        uint32_t aH = st, aL = st + ASZ, bH = st + 2 * ASZ, bL = st + 3 * ASZ;

#pragma unroll
        for (int ks = 0; ks < 2; ks++) {
            int c0 = ks * 16;
            uint32_t ah[4][4], al[4][4], bh[4][2], bl[4][2];
#pragma unroll
            for (int mi = 0; mi < 4; mi++) {
                uint32_t off = (uint32_t)((arow0 + mi * 16) * PITCHB + (colp + c0) * 2);
                LDSM4(ah[mi][0], ah[mi][1], ah[mi][2], ah[mi][3], aH + off);
                LDSM4(al[mi][0], al[mi][1], al[mi][2], al[mi][3], aL + off);
            }
#pragma unroll
            for (int nj = 0; nj < 2; nj++) {
                uint32_t off = (uint32_t)((brow0 + nj * 16) * PITCHB + (colp + c0) * 2);
                uint32_t t0, t1, t2, t3;
                LDSM4(t0, t1, t2, t3, bH + off);
                bh[nj * 2 + 0][0] = t0; bh[nj * 2 + 0][1] = t2;
                bh[nj * 2 + 1][0] = t1; bh[nj * 2 + 1][1] = t3;
                LDSM4(t0, t1, t2, t3, bL + off);
                bl[nj * 2 + 0][0] = t0; bl[nj * 2 + 0][1] = t2;
                bl[nj * 2 + 1][0] = t1; bl[nj * 2 + 1][1] = t3;
            }
#pragma unroll
            for (int mi = 0; mi < 4; mi++)
#pragma unroll
                for (int ni = 0; ni < 4; ni++) {
                    MMA16816(acc[mi][ni], ah[mi], bh[ni]);
                    MMA16816(acc[mi][ni], ah[mi], bl[ni]);
                    MMA16816(acc[mi][ni], al[mi], bh[ni]);
                }
        }
        __syncthreads();
        if (kt + 2 < NK) {
            long long kb = (long long)((kt + 2) * 32) * 2;
#pragma unroll
            for (int i = 0; i < 2; i++) {
                CPA(st + 0 * ASZ + smoff[i], (const char*)Ahi + abyte[i] + kb, asz[i]);
                CPA(st + 1 * ASZ + smoff[i], (const char*)Alo + abyte[i] + kb, asz[i]);
                CPA(st + 2 * ASZ + smoff[i], (const char*)Bhi + bbyte[i] + kb, 16u);
                CPA(st + 3 * ASZ + smoff[i], (const char*)Blo + bbyte[i] + kb, 16u);
            }
        }
        CPA_COMMIT();
    }
    CPA_WAIT0();

    // ---- epilogue ----
    int q = lane >> 2, i2 = (lane & 3) * 2;
#pragma unroll
    for (int mi = 0; mi < 4; mi++) {
        int r0 = bm + warp_m * 64 + mi * 16 + q;
        int r1 = r0 + 8;
        bool ok0 = r0 < Mrows, ok1 = r1 < Mrows;
        long long o0 = ok0 ? (long long)(r0 / c_slv) * c_outer + c_modoff +
                             (long long)(r0 % c_slv) * 1024 : 0;
        long long o1 = ok1 ? (long long)(r1 / c_slv) * c_outer + c_modoff +
                             (long long)(r1 % c_slv) * 1024 : 0;
#pragma unroll
        for (int ni = 0; ni < 4; ni++) {
            int c = bn + warp_n * 32 + ni * 8 + i2;
#pragma unroll
            for (int e = 0; e < 2; e++) {
                int col = c + e;
                float bsum = bias[col] + (bias2 ? bias2[col] : 0.f);
                if (ok0) {
                    float v = acc[mi][ni][e] + bsum;
                    if (Chi) {
                        __nv_bfloat16 h = __float2bfloat16(v);
                        Chi[o0 + col] = h;
                        Clo[o0 + col] = __float2bfloat16(v - __bfloat162float(h));
                    } else Cp[o0 + col] = v;
                }
                if (ok1) {
                    float v = acc[mi][ni][2 + e] + bsum;
                    if (Chi) {
                        __nv_bfloat16 h = __float2bfloat16(v);
                        Chi[o1 + col] = h;
                        Clo[o1 + col] = __float2bfloat16(v - __bfloat162float(h));
                    } else Cp[o1 + col] = v;
                }
            }
        }
    }
}

// ---------------- fused routed attention + mean, pad rows = bias -------------
__global__ void __launch_bounds__(128) attn_fuse_kernel(
    const float* __restrict__ tptr, const float* __restrict__ bq,
    const float* __restrict__ bk, const float* __restrict__ bv)
{
    int s = blockIdx.x;
    int b = blockIdx.z;
    int h = blockIdx.y * 4 + (threadIdx.x >> 5);
    int lane = threadIdx.x & 31;

    float invscale = 1.f / (8.f * fabsf(*tptr));

    int col = h * 64 + lane;
    long long base = ((long long)b * Mm) * Ss * Dd + (long long)s * Dd + col;

    float q0[4], q1[4], k0[4], k1[4], v0[4], v1[4];
#pragma unroll
    for (int m = 0; m < 4; m++) {
        bool live = s < c_sl[m];
        long long idx = base + (long long)m * Ss * Dd;
        q0[m] = live ? g_Q[idx]      : bq[col];
        q1[m] = live ? g_Q[idx + 32] : bq[col + 32];
        k0[m] = live ? g_K[idx]      : bk[col];
        k1[m] = live ? g_K[idx + 32] : bk[col + 32];
        v0[m] = live ? g_V[idx]      : bv[col];
        v1[m] = live ? g_V[idx + 32] : bv[col + 32];
    }

    float acc0 = 0.f, acc1 = 0.f;
#pragma unroll
    for (int m = 0; m < 4; m++) {
        float sc[3];
#pragma unroll
        for (int w = 0; w < 3; w++) {
            int r = c_routes[m][w];
            float p = q0[m] * k0[r] + q1[m] * k1[r];
#pragma unroll
            for (int o = 16; o > 0; o >>= 1) p += __shfl_xor_sync(0xffffffffu, p, o);
            sc[w] = p * invscale;
        }
        float mx = fmaxf(sc[0], fmaxf(sc[1], sc[2]));
        float e0 = expf(sc[0] - mx), e1 = expf(sc[1] - mx), e2 = expf(sc[2] - mx);
        float inv = 1.f / (e0 + e1 + e2);
        e0 *= inv; e1 *= inv; e2 *= inv;
        int r0 = c_routes[m][0], r1 = c_routes[m][1], r2 = c_routes[m][2];
        acc0 += e0 * v0[r0] + e1 * v0[r1] + e2 * v0[r2];
        acc1 += e0 * v1[r0] + e1 * v1[r1] + e2 * v1[r2];
    }

    long long fidx = ((long long)b * Ss + s) * Dd + col;
    float f0 = acc0 * 0.25f, f1 = acc1 * 0.25f;
    __nv_bfloat16 h0 = __float2bfloat16(f0), h1 = __float2bfloat16(f1);
    g_fhi[fidx]      = h0;  g_flo[fidx]      = __float2bfloat16(f0 - __bfloat162float(h0));
    g_fhi[fidx + 32] = h1;  g_flo[fidx + 32] = __float2bfloat16(f1 - __bfloat162float(h1));
}

// ---------------- host launcher ----------------------------------------------
extern "C" void kernel_launch(void* const* d_in, const int* in_sizes, int n_in,
                              void* d_out, int out_size)
{
    bool dictOrder = (in_sizes[1] == 1024 * 768);
    int xi[4], wi[4], bi[4];
    if (dictOrder) {
        int x[4] = {0, 3, 6, 9}, w[4] = {1, 4, 7, 10}, bb[4] = {2, 5, 8, 11};
        for (int i = 0; i < 4; i++) { xi[i] = x[i]; wi[i] = w[i]; bi[i] = bb[i]; }
    } else {
        int x[4] = {0, 1, 2, 3}, w[4] = {4, 6, 8, 10}, bb[4] = {5, 7, 9, 11};
        for (int i = 0; i < 4; i++) { xi[i] = x[i]; wi[i] = w[i]; bi[i] = bb[i]; }
    }
    const float* X[4]; const float* Wmod[4]; const float* bmod[4];
    for (int i = 0; i < 4; i++) {
        X[i]    = (const float*)d_in[xi[i]];
        Wmod[i] = (const float*)d_in[wi[i]];
        bmod[i] = (const float*)d_in[bi[i]];
    }
    const float* mod_emb = (const float*)d_in[12];
    const float* Wq = (const float*)d_in[13]; const float* bq = (const float*)d_in[14];
    const float* Wk = (const float*)d_in[15]; const float* bk = (const float*)d_in[16];
    const float* Wv = (const float*)d_in[17]; const float* bv = (const float*)d_in[18];
    const float* Wo = (const float*)d_in[19]; const float* bo = (const float*)d_in[20];
    const float* tptr = (const float*)d_in[21];

    __nv_bfloat16 *xhi, *xlo, *whi, *wlo, *shi, *slo, *fhi, *flo;
    float *Qb, *Kb, *Vb;
    cudaGetSymbolAddress((void**)&xhi, g_xhi);  cudaGetSymbolAddress((void**)&xlo, g_xlo);
    cudaGetSymbolAddress((void**)&whi, g_whi);  cudaGetSymbolAddress((void**)&wlo, g_wlo);
    cudaGetSymbolAddress((void**)&shi, g_shi);  cudaGetSymbolAddress((void**)&slo, g_slo);
    cudaGetSymbolAddress((void**)&Qb, g_Q);     cudaGetSymbolAddress((void**)&Kb, g_K);
    cudaGetSymbolAddress((void**)&Vb, g_V);
    cudaGetSymbolAddress((void**)&fhi, g_fhi);  cudaGetSymbolAddress((void**)&flo, g_flo);

    cudaFuncSetAttribute(gemm_bf16x2, cudaFuncAttributeMaxDynamicSharedMemorySize, GEMM_SMEM);

    // 1) bf16 hi/lo splits of inputs and weights
    for (int i = 0; i < 4; i++) {
        int n = Bb * h_sls[i] * h_dims[i];
        split_kernel<<<(n + 1023) / 1024, 256>>>(X[i], xhi + h_xoff[i], xlo + h_xoff[i], n);
        int wn = 1024 * h_dims[i];
        split_kernel<<<(wn + 1023) / 1024, 256>>>(Wmod[i], whi + h_woff[i], wlo + h_woff[i], wn);
    }
    const float* Wqkvo[4] = {Wq, Wk, Wv, Wo};
    for (int i = 0; i < 4; i++)
        split_kernel<<<1024, 256>>>(Wqkvo[i], whi + h_woff[4 + i], wlo + h_woff[4 + i],
                                    1024 * 1024);

    // 2) modality projections -> stacked (bf16 hi/lo), live rows only
    for (int i = 0; i < 4; i++) {
        int Mr = Bb * h_sls[i];
        dim3 grid(8, (Mr + 127) / 128);
        gemm_bf16x2<<<grid, 256, GEMM_SMEM>>>(
            xhi + h_xoff[i], xlo + h_xoff[i], 0LL, 0LL, Mr, h_dims[i],
            whi + h_woff[i], wlo + h_woff[i], bmod[i], mod_emb + (long long)i * 1024,
            nullptr, shi, slo,
            Mr, h_dims[i], h_sls[i], (long long)Mm * Ss * Dd, (long long)i * Ss * Dd);
    }

    // 3) QKV projections, per-modality live rows only -> f32
    float* QKV[3] = {Qb, Kb, Vb};
    const float* bqkv[3] = {bq, bk, bv};
    for (int t = 0; t < 3; t++) {
        for (int m = 0; m < 4; m++) {
            int Mr = Bb * h_sls[m];
            dim3 grid(8, (Mr + 127) / 128);
            gemm_bf16x2<<<grid, 256, GEMM_SMEM>>>(
                shi, slo, (long long)Mm * Ss * Dd, (long long)m * Ss * Dd, h_sls[m], 1024,
                whi + h_woff[4 + t], wlo + h_woff[4 + t], bqkv[t], nullptr,
                QKV[t], nullptr, nullptr,
                Mr, 1024, h_sls[m], (long long)Mm * Ss * Dd, (long long)m * Ss * Dd);
        }
    }

    // 4) fused routed attention + modality mean -> fused (bf16 hi/lo)
    {
        dim3 grid(Ss, Hh / 4, Bb);
        attn_fuse_kernel<<<grid, 128>>>(tptr, bq, bk, bv);
    }

    // 5) output projection: out = fused @ Wo^T + bo -> f32 d_out
    {
        int Mr = Bb * Ss;
        dim3 grid(8, Mr / 128);
        gemm_bf16x2<<<grid, 256, GEMM_SMEM>>>(
            fhi, flo, 0LL, 0LL, Mr, 1024,
            whi + h_woff[7], wlo + h_woff[7], bo, nullptr,
            (float*)d_out, nullptr, nullptr,
            Mr, 1024, Mr, 0LL, 0LL);
    }
}

// round 12
// speedup vs baseline: 2.8908x; 1.1038x over previous
#include <cuda_runtime.h>
#include <cuda_bf16.h>
#include <math.h>
#include <stdint.h>

#define Bb 4
#define Ss 2048
#define Dd 1024
#define Hh 16
#define Mm 4

#define BMSD (4LL*4*2048*1024)
#define BSD  (4LL*2048*1024)

static const int h_dims[4] = {768, 1024, 512, 2048};
static const int h_sls[4]  = {2048, 1024, 1500, 512};
static const long long h_xoff[4] = {0, 6291456, 10485760, 13557760};
#define XTOT 17752064
static const long long h_woff[8] = {0, 786432, 1835008, 2359296, 4456448, 5505024, 6553600, 7602176};
#define WTOT 8650752

// ---------------- scratch (device globals) -----------------------------------
__device__ __nv_bfloat16 g_xhi[XTOT], g_xlo[XTOT];
__device__ __nv_bfloat16 g_whi[WTOT], g_wlo[WTOT];
__device__ __nv_bfloat16 g_shi[BMSD], g_slo[BMSD];
__device__ float g_Q[BMSD], g_K[BMSD], g_V[BMSD];
__device__ __nv_bfloat16 g_fhi[BSD], g_flo[BSD];

// Cantor routes (exact-double semantics): coords = [0, 0, 0.5, 0.99609375]
__constant__ int c_routes[4][3] = {{0, 1, 2}, {0, 1, 2}, {2, 3, 0}, {3, 2, 0}};
__constant__ int c_sl[4] = {2048, 1024, 1500, 512};

// ---------------- helpers -----------------------------------------------------
__device__ __forceinline__ uint32_t smem_u32(const void* p) {
    uint32_t a;
    asm("{ .reg .u64 t; cvta.to.shared.u64 t, %1; cvt.u32.u64 %0, t; }" : "=r"(a) : "l"(p));
    return a;
}

#define CPA(sa, ga, sz) \
    asm volatile("cp.async.cg.shared.global [%0], [%1], 16, %2;" \
                 :: "r"(sa), "l"(ga), "r"(sz) : "memory")
#define CPA_COMMIT() asm volatile("cp.async.commit_group;" ::: "memory")
#define CPA_WAIT1()  asm volatile("cp.async.wait_group 1;" ::: "memory")

#define LDSM4(r0, r1, r2, r3, addr) \
    asm volatile("ldmatrix.sync.aligned.m8n8.x4.shared.b16 {%0,%1,%2,%3}, [%4];" \
                 : "=r"(r0), "=r"(r1), "=r"(r2), "=r"(r3) : "r"(addr))

#define MMA16816(d, a, b) \
    asm volatile("mma.sync.aligned.m16n8k16.row.col.f32.bf16.bf16.f32 " \
                 "{%0,%1,%2,%3}, {%4,%5,%6,%7}, {%8,%9}, {%0,%1,%2,%3};" \
                 : "+f"((d)[0]), "+f"((d)[1]), "+f"((d)[2]), "+f"((d)[3]) \
                 : "r"((a)[0]), "r"((a)[1]), "r"((a)[2]), "r"((a)[3]), \
                   "r"((b)[0]), "r"((b)[1]))

// ---------------- merged bf16 hi/lo split (12 segments, one launch) ----------
struct SplitSegs {
    const float* src[12];
    __nv_bfloat16* hi[12];
    __nv_bfloat16* lo[12];
    long long start[13];   // cumulative element offsets; start[12] = total
};

__global__ void split_all_kernel(SplitSegs segs) {
    long long total = segs.start[12];
    for (long long i = (long long)blockIdx.x * blockDim.x + threadIdx.x; i < total;
         i += (long long)gridDim.x * blockDim.x) {
        int seg = 0;
#pragma unroll
        for (int s = 1; s < 12; s++) seg += (i >= segs.start[s]) ? 1 : 0;
        long long local = i - segs.start[seg];
        float x = segs.src[seg][local];
        __nv_bfloat16 h = __float2bfloat16(x);
        segs.hi[seg][local] = h;
        segs.lo[seg][local] = __float2bfloat16(x - __bfloat162float(h));
    }
}

// ---------------- bf16x2 mma.sync GEMM: C = A @ W^T (+bias,+bias2) -----------
// 128x128 tile, 256 threads (8 warps, warp tile 64x32), BK=32,
// 3-stage cp.async ring with a SINGLE __syncthreads per iteration.
// A row r reads A + r*lda (identity). liveMode 1 = modality liveness on
// flattened (b,m,s) rows; dead rows are zero-filled / not written.
// C row r: (r/c_sl)*c_outer + c_modoff + (r%c_sl)*1024.
#define PITCHB 80
#define ASZ (128 * PITCHB)          // 10240 per array
#define STAGE_SZ (4 * ASZ)          // Ah, Al, Bh, Bl = 40960
#define GEMM_SMEM (3 * STAGE_SZ)    // 122880

__global__ void __launch_bounds__(256, 1) gemm_bf16x2(
    const __nv_bfloat16* __restrict__ Ahi, const __nv_bfloat16* __restrict__ Alo,
    int lda,
    const __nv_bfloat16* __restrict__ Bhi, const __nv_bfloat16* __restrict__ Blo,
    const float* __restrict__ bias, const float* __restrict__ bias2,
    float* __restrict__ Cp, __nv_bfloat16* __restrict__ Chi, __nv_bfloat16* __restrict__ Clo,
    int Mrows, int K, int liveMode, int c_slv, long long c_outer, long long c_modoff)
{
    extern __shared__ char smem[];
    const uint32_t sbase = smem_u32(smem);
    int tid = threadIdx.x, wid = tid >> 5, lane = tid & 31;
    int warp_m = wid & 1, warp_n = wid >> 1;
    int bm = blockIdx.y * 128, bn = blockIdx.x * 128;

    // dead-block early exit (liveMode=1: 128 rows share one (b,m))
    if (liveMode && ((bm & 2047) >= c_sl[(bm >> 11) & 3])) return;

    // ---- load slots: 2 per thread per array (128 rows x 4 chunks of 16B) ----
    uint32_t smoff[2];
    long long abyte[2], bbyte[2];
    uint32_t asz[2];
#pragma unroll
    for (int i = 0; i < 2; i++) {
        int s = tid + i * 256;
        int row = s >> 2, ch = s & 3;
        smoff[i] = (uint32_t)(row * PITCHB + ch * 16);
        int gr = bm + row;
        bool av = (gr < Mrows) &&
                  (!liveMode || ((gr & 2047) < c_sl[(gr >> 11) & 3]));
        asz[i] = av ? 16u : 0u;
        abyte[i] = av ? ((long long)gr * lda + ch * 8) * 2 : 0;
        bbyte[i] = ((long long)(bn + row) * K + ch * 8) * 2;
    }

    const int NK = K >> 5;

    auto issue = [&](int kt2) {
        uint32_t st = sbase + (uint32_t)(kt2 % 3) * STAGE_SZ;
        long long kb = (long long)kt2 * 64;   // 32 bf16 = 64 bytes
#pragma unroll
        for (int i = 0; i < 2; i++) {
            CPA(st + 0 * ASZ + smoff[i], (const char*)Ahi + abyte[i] + kb, asz[i]);
            CPA(st + 1 * ASZ + smoff[i], (const char*)Alo + abyte[i] + kb, asz[i]);
            CPA(st + 2 * ASZ + smoff[i], (const char*)Bhi + bbyte[i] + kb, 16u);
            CPA(st + 3 * ASZ + smoff[i], (const char*)Blo + bbyte[i] + kb, 16u);
        }
    };

    // prologue: stages 0,1
    issue(0); CPA_COMMIT();
    issue(1); CPA_COMMIT();

    float acc[4][4][4];
#pragma unroll
    for (int a = 0; a < 4; a++)
#pragma unroll
        for (int b = 0; b < 4; b++)
#pragma unroll
            for (int c = 0; c < 4; c++) acc[a][b][c] = 0.f;

    // ldmatrix lane addressing
    int lrow = lane & 7, lsel = lane >> 3;
    int arow0 = warp_m * 64 + ((lsel & 1) << 3) + lrow;
    int brow0 = warp_n * 32 + ((lsel & 1) << 3) + lrow;
    int colp  = (lsel >> 1) << 3;    // 0 or 8 (element col within k16)

    for (int kt = 0; kt < NK; ++kt) {
        CPA_WAIT1();
        __syncthreads();
        if (kt + 2 < NK) issue(kt + 2);
        CPA_COMMIT();

        uint32_t st = sbase + (uint32_t)(kt % 3) * STAGE_SZ;
        uint32_t aH = st, aL = st + ASZ, bH = st + 2 * ASZ, bL = st + 3 * ASZ;

#pragma unroll
        for (int ks = 0; ks < 2; ks++) {
            int c0 = ks * 16;
            uint32_t ah[4][4], al[4][4], bh[4][2], bl[4][2];
#pragma unroll
            for (int mi = 0; mi < 4; mi++) {
                uint32_t off = (uint32_t)((arow0 + mi * 16) * PITCHB + (colp + c0) * 2);
                LDSM4(ah[mi][0], ah[mi][1], ah[mi][2], ah[mi][3], aH + off);
                LDSM4(al[mi][0], al[mi][1], al[mi][2], al[mi][3], aL + off);
            }
#pragma unroll
            for (int nj = 0; nj < 2; nj++) {
                uint32_t off = (uint32_t)((brow0 + nj * 16) * PITCHB + (colp + c0) * 2);
                uint32_t t0, t1, t2, t3;
                LDSM4(t0, t1, t2, t3, bH + off);
                bh[nj * 2 + 0][0] = t0; bh[nj * 2 + 0][1] = t2;
                bh[nj * 2 + 1][0] = t1; bh[nj * 2 + 1][1] = t3;
                LDSM4(t0, t1, t2, t3, bL + off);
                bl[nj * 2 + 0][0] = t0; bl[nj * 2 + 0][1] = t2;
                bl[nj * 2 + 1][0] = t1; bl[nj * 2 + 1][1] = t3;
            }
#pragma unroll
            for (int mi = 0; mi < 4; mi++)
#pragma unroll
                for (int ni = 0; ni < 4; ni++) {
                    MMA16816(acc[mi][ni], ah[mi], bh[ni]);
                    MMA16816(acc[mi][ni], ah[mi], bl[ni]);
                    MMA16816(acc[mi][ni], al[mi], bh[ni]);
                }
        }
    }

    // ---- epilogue ----
    int q = lane >> 2, i2 = (lane & 3) * 2;
#pragma unroll
    for (int mi = 0; mi < 4; mi++) {
        int r0 = bm + warp_m * 64 + mi * 16 + q;
        int r1 = r0 + 8;
        bool ok0 = (r0 < Mrows) && (!liveMode || ((r0 & 2047) < c_sl[(r0 >> 11) & 3]));
        bool ok1 = (r1 < Mrows) && (!liveMode || ((r1 & 2047) < c_sl[(r1 >> 11) & 3]));
        long long o0 = ok0 ? (long long)(r0 / c_slv) * c_outer + c_modoff +
                             (long long)(r0 % c_slv) * 1024 : 0;
        long long o1 = ok1 ? (long long)(r1 / c_slv) * c_outer + c_modoff +
                             (long long)(r1 % c_slv) * 1024 : 0;
#pragma unroll
        for (int ni = 0; ni < 4; ni++) {
            int c = bn + warp_n * 32 + ni * 8 + i2;
#pragma unroll
            for (int e = 0; e < 2; e++) {
                int col = c + e;
                float bsum = bias[col] + (bias2 ? bias2[col] : 0.f);
                if (ok0) {
                    float v = acc[mi][ni][e] + bsum;
                    if (Chi) {
                        __nv_bfloat16 h = __float2bfloat16(v);
                        Chi[o0 + col] = h;
                        Clo[o0 + col] = __float2bfloat16(v - __bfloat162float(h));
                    } else Cp[o0 + col] = v;
                }
                if (ok1) {
                    float v = acc[mi][ni][2 + e] + bsum;
                    if (Chi) {
                        __nv_bfloat16 h = __float2bfloat16(v);
                        Chi[o1 + col] = h;
                        Clo[o1 + col] = __float2bfloat16(v - __bfloat162float(h));
                    } else Cp[o1 + col] = v;
                }
            }
        }
    }
}

// ---------------- fused routed attention + mean, pad rows = bias -------------
__global__ void __launch_bounds__(128) attn_fuse_kernel(
    const float* __restrict__ tptr, const float* __restrict__ bq,
    const float* __restrict__ bk, const float* __restrict__ bv)
{
    int s = blockIdx.x;
    int b = blockIdx.z;
    int h = blockIdx.y * 4 + (threadIdx.x >> 5);
    int lane = threadIdx.x & 31;

    float invscale = 1.f / (8.f * fabsf(*tptr));

    int col = h * 64 + lane;
    long long base = ((long long)b * Mm) * Ss * Dd + (long long)s * Dd + col;

    float q0[4], q1[4], k0[4], k1[4], v0[4], v1[4];
#pragma unroll
    for (int m = 0; m < 4; m++) {
        bool live = s < c_sl[m];
        long long idx = base + (long long)m * Ss * Dd;
        q0[m] = live ? g_Q[idx]      : bq[col];
        q1[m] = live ? g_Q[idx + 32] : bq[col + 32];
        k0[m] = live ? g_K[idx]      : bk[col];
        k1[m] = live ? g_K[idx + 32] : bk[col + 32];
        v0[m] = live ? g_V[idx]      : bv[col];
        v1[m] = live ? g_V[idx + 32] : bv[col + 32];
    }

    float acc0 = 0.f, acc1 = 0.f;
#pragma unroll
    for (int m = 0; m < 4; m++) {
        float sc[3];
#pragma unroll
        for (int w = 0; w < 3; w++) {
            int r = c_routes[m][w];
            float p = q0[m] * k0[r] + q1[m] * k1[r];
#pragma unroll
            for (int o = 16; o > 0; o >>= 1) p += __shfl_xor_sync(0xffffffffu, p, o);
            sc[w] = p * invscale;
        }
        float mx = fmaxf(sc[0], fmaxf(sc[1], sc[2]));
        float e0 = expf(sc[0] - mx), e1 = expf(sc[1] - mx), e2 = expf(sc[2] - mx);
        float inv = 1.f / (e0 + e1 + e2);
        e0 *= inv; e1 *= inv; e2 *= inv;
        int r0 = c_routes[m][0], r1 = c_routes[m][1], r2 = c_routes[m][2];
        acc0 += e0 * v0[r0] + e1 * v0[r1] + e2 * v0[r2];
        acc1 += e0 * v1[r0] + e1 * v1[r1] + e2 * v1[r2];
    }

    long long fidx = ((long long)b * Ss + s) * Dd + col;
    float f0 = acc0 * 0.25f, f1 = acc1 * 0.25f;
    __nv_bfloat16 h0 = __float2bfloat16(f0), h1 = __float2bfloat16(f1);
    g_fhi[fidx]      = h0;  g_flo[fidx]      = __float2bfloat16(f0 - __bfloat162float(h0));
    g_fhi[fidx + 32] = h1;  g_flo[fidx + 32] = __float2bfloat16(f1 - __bfloat162float(h1));
}

// ---------------- host launcher ----------------------------------------------
extern "C" void kernel_launch(void* const* d_in, const int* in_sizes, int n_in,
                              void* d_out, int out_size)
{
    bool dictOrder = (in_sizes[1] == 1024 * 768);
    int xi[4], wi[4], bi[4];
    if (dictOrder) {
        int x[4] = {0, 3, 6, 9}, w[4] = {1, 4, 7, 10}, bb[4] = {2, 5, 8, 11};
        for (int i = 0; i < 4; i++) { xi[i] = x[i]; wi[i] = w[i]; bi[i] = bb[i]; }
    } else {
        int x[4] = {0, 1, 2, 3}, w[4] = {4, 6, 8, 10}, bb[4] = {5, 7, 9, 11};
        for (int i = 0; i < 4; i++) { xi[i] = x[i]; wi[i] = w[i]; bi[i] = bb[i]; }
    }
    const float* X[4]; const float* Wmod[4]; const float* bmod[4];
    for (int i = 0; i < 4; i++) {
        X[i]    = (const float*)d_in[xi[i]];
        Wmod[i] = (const float*)d_in[wi[i]];
        bmod[i] = (const float*)d_in[bi[i]];
    }
    const float* mod_emb = (const float*)d_in[12];
    const float* Wq = (const float*)d_in[13]; const float* bq = (const float*)d_in[14];
    const float* Wk = (const float*)d_in[15]; const float* bk = (const float*)d_in[16];
    const float* Wv = (const float*)d_in[17]; const float* bv = (const float*)d_in[18];
    const float* Wo = (const float*)d_in[19]; const float* bo = (const float*)d_in[20];
    const float* tptr = (const float*)d_in[21];

    __nv_bfloat16 *xhi, *xlo, *whi, *wlo, *shi, *slo, *fhi, *flo;
    float *Qb, *Kb, *Vb;
    cudaGetSymbolAddress((void**)&xhi, g_xhi);  cudaGetSymbolAddress((void**)&xlo, g_xlo);
    cudaGetSymbolAddress((void**)&whi, g_whi);  cudaGetSymbolAddress((void**)&wlo, g_wlo);
    cudaGetSymbolAddress((void**)&shi, g_shi);  cudaGetSymbolAddress((void**)&slo, g_slo);
    cudaGetSymbolAddress((void**)&Qb, g_Q);     cudaGetSymbolAddress((void**)&Kb, g_K);
    cudaGetSymbolAddress((void**)&Vb, g_V);
    cudaGetSymbolAddress((void**)&fhi, g_fhi);  cudaGetSymbolAddress((void**)&flo, g_flo);

    cudaFuncSetAttribute(gemm_bf16x2, cudaFuncAttributeMaxDynamicSharedMemorySize, GEMM_SMEM);

    // 1) all bf16 hi/lo splits in ONE launch
    {
        SplitSegs segs;
        long long cum = 0;
        for (int i = 0; i < 4; i++) {
            segs.src[i] = X[i];
            segs.hi[i] = xhi + h_xoff[i];
            segs.lo[i] = xlo + h_xoff[i];
            segs.start[i] = cum;
            cum += (long long)Bb * h_sls[i] * h_dims[i];
        }
        const float* Wall[8] = {Wmod[0], Wmod[1], Wmod[2], Wmod[3], Wq, Wk, Wv, Wo};
        for (int i = 0; i < 8; i++) {
            segs.src[4 + i] = Wall[i];
            segs.hi[4 + i] = whi + h_woff[i];
            segs.lo[4 + i] = wlo + h_woff[i];
            segs.start[4 + i] = cum;
            cum += (i < 4) ? (long long)1024 * h_dims[i] : 1024LL * 1024;
        }
        segs.start[12] = cum;
        split_all_kernel<<<2048, 256>>>(segs);
    }

    // 2) modality projections -> stacked (bf16 hi/lo)
    for (int i = 0; i < 4; i++) {
        int Mr = Bb * h_sls[i];
        dim3 grid(8, (Mr + 127) / 128);
        gemm_bf16x2<<<grid, 256, GEMM_SMEM>>>(
            xhi + h_xoff[i], xlo + h_xoff[i], h_dims[i],
            whi + h_woff[i], wlo + h_woff[i], bmod[i], mod_emb + (long long)i * 1024,
            nullptr, shi, slo,
            Mr, h_dims[i], 0, h_sls[i], (long long)Mm * Ss * Dd, (long long)i * Ss * Dd);
    }

    // 3) QKV projections: one full-range launch per tensor, modality liveness
    float* QKV[3] = {Qb, Kb, Vb};
    const float* bqkv[3] = {bq, bk, bv};
    for (int t = 0; t < 3; t++) {
        dim3 grid(8, (Bb * Mm * Ss) / 128);   // 8 x 256
        gemm_bf16x2<<<grid, 256, GEMM_SMEM>>>(
            shi, slo, 1024,
            whi + h_woff[4 + t], wlo + h_woff[4 + t], bqkv[t], nullptr,
            QKV[t], nullptr, nullptr,
            Bb * Mm * Ss, 1024, 1, 1 << 30, 0LL, 0LL);
    }

    // 4) fused routed attention + modality mean -> fused (bf16 hi/lo)
    {
        dim3 grid(Ss, Hh / 4, Bb);
        attn_fuse_kernel<<<grid, 128>>>(tptr, bq, bk, bv);
    }

    // 5) output projection: out = fused @ Wo^T + bo -> f32 d_out
    {
        int Mr = Bb * Ss;
        dim3 grid(8, Mr / 128);
        gemm_bf16x2<<<grid, 256, GEMM_SMEM>>>(
            fhi, flo, 1024,
            whi + h_woff[7], wlo + h_woff[7], bo, nullptr,
            (float*)d_out, nullptr, nullptr,
            Mr, 1024, 0, 1 << 30, 0LL, 0LL);
    }
}